// round 3
// baseline (speedup 1.0000x reference)
#include <cuda_runtime.h>
#include <math.h>

#define N_NODES 50000
#define N_EDGES 800000
#define NUM_RELS 16
#define H_DIM 128
#define LIN_DIM 512

#define CAP1 256
#define CAP2 2048
#define CAPE1 512
#define CAPE2 4096

#define BM_WORDS ((N_NODES + 31) / 32)   // 1563

#define NB 296                            // 2 blocks/SM on 148 SMs (guaranteed resident)
#define NT 256
#define GT (NB * NT)

// ---------------- scratch (device globals; no allocation) ----------------
__device__ int          g_slot1[N_NODES];
__device__ int          g_slot2[N_NODES];
__device__ unsigned int g_bm1[BM_WORDS + 1];
__device__ unsigned int g_bm2[BM_WORDS + 1];
__device__ int   g_n1, g_n2, g_ne1, g_ne2;
__device__ int   g_s1_nodes[CAP1];
__device__ int   g_s2_nodes[CAP2];
__device__ int   g_e1_src[CAPE1];
__device__ int   g_e2_src[CAPE2];
__device__ int   g_e2_dslot[CAPE2];
__device__ float g_T0[NUM_RELS * H_DIM];
__device__ float g_h1acc[CAP2 * H_DIM];
__device__ float g_h2acc[CAP1 * H_DIM];
__device__ float g_msg1[CAP2 * H_DIM];
__device__ float g_msg2[CAP1 * H_DIM];

// software grid barrier state (zero-initialized; gen persists across replays,
// handled by reading it at kernel entry)
__device__ unsigned g_bar_cnt;
__device__ unsigned g_bar_gen;

// All threads fence their own writes, then thread0 arrives; sense = generation counter.
#define GRID_SYNC()                                                         \
    do {                                                                    \
        __threadfence();                                                    \
        __syncthreads();                                                    \
        if (threadIdx.x == 0) {                                             \
            if (atomicAdd(&g_bar_cnt, 1u) == (unsigned)(NB - 1)) {          \
                *(volatile unsigned*)&g_bar_cnt = 0u;                       \
                __threadfence();                                            \
                *(volatile unsigned*)&g_bar_gen = my_gen + 1u;              \
            } else {                                                        \
                while (*(volatile unsigned*)&g_bar_gen == my_gen)           \
                    __nanosleep(32);                                        \
            }                                                               \
            my_gen++;                                                       \
        }                                                                   \
        __syncthreads();                                                    \
    } while (0)

__global__ void __launch_bounds__(NT, 2) k_fused(
    const int* __restrict__ cls, const float* __restrict__ norm,
    const int* __restrict__ src, const int* __restrict__ dst,
    const float* __restrict__ W0, const float* __restrict__ W1,
    const float* __restrict__ W2,
    const float* __restrict__ a1_w, const float* __restrict__ a1_b,
    const float* __restrict__ a2_w, const float* __restrict__ a2_b,
    const float* __restrict__ c1_w, const float* __restrict__ c1_b,
    const float* __restrict__ c2_w, const float* __restrict__ c2_b,
    float* __restrict__ out, int out_size)
{
    const int tx   = threadIdx.x;
    const int bid  = blockIdx.x;
    const int gtid = bid * NT + tx;
    const int lane = tx & 31;

    unsigned my_gen = 0;
    if (tx == 0) my_gen = *(volatile unsigned*)&g_bar_gen;

    __shared__ float sh2[2][H_DIM];
    __shared__ float s_red[H_DIM];
    __shared__ float s_hid[LIN_DIM];
    __shared__ float s_part[NT];
    __shared__ float s_mx, s_sum;

    // ---------------- phase 0: clear + build T0 ----------------
    {
        const float4 z = make_float4(0.f, 0.f, 0.f, 0.f);
        const int4 m1 = make_int4(-1, -1, -1, -1);
        for (int i = gtid; i < (CAP2 * H_DIM) / 4; i += GT) {
            reinterpret_cast<float4*>(g_h1acc)[i] = z;
            if (i < (CAP1 * H_DIM) / 4) reinterpret_cast<float4*>(g_h2acc)[i] = z;
            if (i < N_NODES / 4) {
                reinterpret_cast<int4*>(g_slot1)[i] = m1;
                reinterpret_cast<int4*>(g_slot2)[i] = m1;
            }
            if (i <= BM_WORDS) { g_bm1[i] = 0u; g_bm2[i] = 0u; }
            if (i < NUM_RELS * H_DIM) {
                int r = i >> 7, j = i & 127;
                g_T0[i] = W0[(r * NUM_RELS + r) * H_DIM + j];  // one-hot @ W0[r]
            }
        }
        if (gtid == 0) { g_n1 = 0; g_n2 = 0; g_ne1 = 0; g_ne2 = 0; }
    }
    GRID_SYNC();

    // ---------------- phase 1: scan edges, dst == 0 -> S1/E1 ----------------
    {
        const int NQ = N_EDGES / 4;
        for (int i = gtid; i < NQ; i += GT) {
            const int4 d4 = reinterpret_cast<const int4*>(dst)[i];
            int dv[4] = {d4.x, d4.y, d4.z, d4.w};
#pragma unroll
            for (int k = 0; k < 4; k++) {
                if (dv[k] == 0) {
                    int s = src[4 * i + k];
                    int p = atomicAdd(&g_ne1, 1);
                    if (p < CAPE1) g_e1_src[p] = s;
                    if (atomicCAS(&g_slot1[s], -1, -2) == -1) {
                        int sl = atomicAdd(&g_n1, 1);
                        if (sl < CAP1) g_s1_nodes[sl] = s;
                        g_slot1[s] = sl;
                        atomicOr(&g_bm1[s >> 5], 1u << (s & 31));
                    }
                }
            }
        }
    }
    GRID_SYNC();

    // ---------------- phase 2: scan edges, dst in S1 -> S2/E2 ----------------
    {
        const int NQ = N_EDGES / 4;
        for (int i = gtid; i < NQ; i += GT) {
            const int4 d4 = reinterpret_cast<const int4*>(dst)[i];
            int dv[4] = {d4.x, d4.y, d4.z, d4.w};
#pragma unroll
            for (int k = 0; k < 4; k++) {
                int d = dv[k];
                if (g_bm1[d >> 5] & (1u << (d & 31))) {
                    int sl = g_slot1[d];
                    if (sl >= 0 && sl < CAP1) {
                        int s = src[4 * i + k];
                        int p = atomicAdd(&g_ne2, 1);
                        if (p < CAPE2) { g_e2_src[p] = s; g_e2_dslot[p] = sl; }
                        if (atomicCAS(&g_slot2[s], -1, -2) == -1) {
                            int q = atomicAdd(&g_n2, 1);
                            if (q < CAP2) g_s2_nodes[q] = s;
                            g_slot2[s] = q;
                            atomicOr(&g_bm2[s >> 5], 1u << (s & 31));
                        }
                    }
                }
            }
        }
    }
    GRID_SYNC();

    // ---------------- phase 3: scan edges, dst in S2 -> accumulate msg0 ----------------
    // h1acc[slot2[dst]] += T0[cls[src]] * norm[src]   (warp-cooperative on hits)
    {
        const int NQ = N_EDGES / 4;
        const int trips = (NQ + GT - 1) / GT;   // uniform across all threads
        for (int t = 0; t < trips; t++) {
            int i = gtid + t * GT;
            bool valid = (i < NQ);
            int dv[4] = {-1, -1, -1, -1};
            if (valid) {
                const int4 d4 = reinterpret_cast<const int4*>(dst)[i];
                dv[0] = d4.x; dv[1] = d4.y; dv[2] = d4.z; dv[3] = d4.w;
            }
#pragma unroll
            for (int k = 0; k < 4; k++) {
                int d = dv[k];
                bool hit = (d >= 0) && (g_bm2[d >> 5] & (1u << (d & 31)));
                unsigned mask = __ballot_sync(0xffffffffu, hit);
                if (mask == 0) continue;
                int my_sl = -1, my_s = 0;
                if (hit) { my_sl = g_slot2[d]; my_s = src[4 * i + k]; }
                while (mask) {
                    int h = __ffs(mask) - 1;
                    mask &= mask - 1;
                    int sl = __shfl_sync(0xffffffffu, my_sl, h);
                    int s  = __shfl_sync(0xffffffffu, my_s, h);
                    if (sl < 0 || sl >= CAP2) continue;
                    int c = cls[s];
                    float nm = norm[s];
                    const float* t0 = &g_T0[c * H_DIM];
                    float* acc = &g_h1acc[sl * H_DIM];
#pragma unroll
                    for (int j = 0; j < 4; j++) {
                        int col = lane + j * 32;
                        atomicAdd(acc + col, t0[col] * nm);
                    }
                }
            }
        }
    }
    GRID_SYNC();

    // ---------------- phase 4: msg1 = (relu(h1acc) @ W1[cls]) * norm  for S2 ----------------
    {
        int n = min(g_n2, CAP2);
        const int per = NB * 2;
        const int iters = (n + per - 1) / per;
        int grp = tx >> 7;       // 0 or 1
        int j   = tx & 127;
        for (int it = 0; it < iters; it++) {
            int sl = it * per + bid * 2 + grp;
            bool act = (sl < n);
            if (act) sh2[grp][j] = fmaxf(g_h1acc[sl * H_DIM + j], 0.f);
            __syncthreads();
            if (act) {
                int node = g_s2_nodes[sl];
                int c = cls[node];
                float nm = norm[node];
                const float* Wc = W1 + c * H_DIM * H_DIM;
                float a = 0.f;
#pragma unroll 8
                for (int k = 0; k < H_DIM; k++) a = fmaf(sh2[grp][k], Wc[k * H_DIM + j], a);
                g_msg1[sl * H_DIM + j] = a * nm;
            }
            __syncthreads();
        }
    }
    GRID_SYNC();

    // ---------------- phase 5: h2acc[dslot] += msg1[slot2[src]]  over E2 ----------------
    {
        int ne = min(g_ne2, CAPE2);
        int wid_g = gtid >> 5;
        int nwarps = GT >> 5;
        for (int e = wid_g; e < ne; e += nwarps) {
            int s   = g_e2_src[e];
            int dsl = g_e2_dslot[e];
            int ssl = g_slot2[s];
            if (ssl < 0 || ssl >= CAP2 || dsl >= CAP1) continue;
            const float* m = &g_msg1[ssl * H_DIM];
            float* a = &g_h2acc[dsl * H_DIM];
#pragma unroll
            for (int j = lane; j < H_DIM; j += 32) atomicAdd(a + j, m[j]);
        }
    }
    GRID_SYNC();

    // ---------------- phase 6: msg2 = (relu(h2acc) @ W2[cls]) * norm  for S1 ----------------
    {
        int n = min(g_n1, CAP1);
        const int per = NB * 2;
        const int iters = (n + per - 1) / per;
        int grp = tx >> 7;
        int j   = tx & 127;
        for (int it = 0; it < iters; it++) {
            int sl = it * per + bid * 2 + grp;
            bool act = (sl < n);
            if (act) sh2[grp][j] = fmaxf(g_h2acc[sl * H_DIM + j], 0.f);
            __syncthreads();
            if (act) {
                int node = g_s1_nodes[sl];
                int c = cls[node];
                float nm = norm[node];
                const float* Wc = W2 + c * H_DIM * H_DIM;
                float a = 0.f;
#pragma unroll 8
                for (int k = 0; k < H_DIM; k++) a = fmaf(sh2[grp][k], Wc[k * H_DIM + j], a);
                g_msg2[sl * H_DIM + j] = a * nm;
            }
            __syncthreads();
        }
    }
    GRID_SYNC();

    // ---------------- phase 7: node-0 aggregate, softmax, heads (block 0 only) ----------------
    if (bid != 0) return;
    {
        int t = tx;
        if (t < H_DIM) {
            float a = 0.f;
            int ne = min(g_ne1, CAPE1);
            for (int i = 0; i < ne; i++) {
                int s  = g_e1_src[i];
                int sl = g_slot1[s];
                if (sl >= 0 && sl < CAP1) a += g_msg2[sl * H_DIM + t];
            }
            s_red[t] = a;
        }
        __syncthreads();
        if (t == 0) {
            float mx = -1e30f;
            for (int i = 0; i < H_DIM; i++) mx = fmaxf(mx, s_red[i]);
            s_mx = mx;
        }
        __syncthreads();
        if (t < H_DIM) s_red[t] = expf(s_red[t] - s_mx);
        __syncthreads();
        if (t == 0) {
            float sm = 0.f;
            for (int i = 0; i < H_DIM; i++) sm += s_red[i];
            s_sum = sm;
        }
        __syncthreads();
        if (t < H_DIM) s_red[t] = s_red[t] / s_sum;   // root feats
        __syncthreads();

        // actor: 128 -> 512 relu -> 128
        for (int u = t; u < LIN_DIM; u += NT) {
            float a = a1_b[u];
#pragma unroll 8
            for (int k = 0; k < H_DIM; k++) a = fmaf(s_red[k], a1_w[k * LIN_DIM + u], a);
            s_hid[u] = fmaxf(a, 0.f);
        }
        __syncthreads();
        if (t < H_DIM) {
            float a = a2_b[t];
#pragma unroll 8
            for (int k = 0; k < LIN_DIM; k++) a = fmaf(s_hid[k], a2_w[k * H_DIM + t], a);
            out[t] = a;
        }
        __syncthreads();

        // critic: 128 -> 512 relu -> 1
        for (int u = t; u < LIN_DIM; u += NT) {
            float a = c1_b[u];
#pragma unroll 8
            for (int k = 0; k < H_DIM; k++) a = fmaf(s_red[k], c1_w[k * LIN_DIM + u], a);
            s_hid[u] = fmaxf(a, 0.f);
        }
        __syncthreads();
        {
            float p = 0.f;
            for (int u = t; u < LIN_DIM; u += NT) p = fmaf(s_hid[u], c2_w[u], p);
            s_part[t] = p;
        }
        __syncthreads();
        if (t == 0) {
            float a = c2_b[0];
            for (int i = 0; i < NT; i++) a += s_part[i];
            if (out_size > H_DIM) out[H_DIM] = a;
        }
    }
}

// ---------------- launch ----------------
extern "C" void kernel_launch(void* const* d_in, const int* in_sizes, int n_in,
                              void* d_out, int out_size) {
    const int*   cls  = (const int*)  d_in[0];
    const float* norm = (const float*)d_in[1];
    const int*   src  = (const int*)  d_in[2];
    const int*   dst  = (const int*)  d_in[3];
    const float* W0   = (const float*)d_in[4];
    const float* W1   = (const float*)d_in[5];
    const float* W2   = (const float*)d_in[6];
    const float* a1_w = (const float*)d_in[7];
    const float* a1_b = (const float*)d_in[8];
    const float* a2_w = (const float*)d_in[9];
    const float* a2_b = (const float*)d_in[10];
    const float* c1_w = (const float*)d_in[11];
    const float* c1_b = (const float*)d_in[12];
    const float* c2_w = (const float*)d_in[13];
    const float* c2_b = (const float*)d_in[14];
    float* out = (float*)d_out;

    k_fused<<<NB, NT>>>(cls, norm, src, dst, W0, W1, W2,
                        a1_w, a1_b, a2_w, a2_b, c1_w, c1_b, c2_w, c2_b,
                        out, out_size);
}

// round 4
// speedup vs baseline: 1.0827x; 1.0827x over previous
#include <cuda_runtime.h>
#include <math.h>

#define N_NODES 50000
#define N_EDGES 800000
#define NUM_RELS 16
#define H_DIM 128
#define LIN_DIM 512

#define CAP1 256
#define CAP2 2048
#define CAPE1 512
#define CAPE2 4096

#define BM_WORDS ((N_NODES + 31) / 32)   // 1563

#define NB 444                            // 3 blocks/SM on 148 SMs
#define NT 512
#define GT (NB * NT)
#define NQ (N_EDGES / 4)                  // 200000 int4 quads

// ---------------- scratch (device globals; no allocation) ----------------
__device__ int          g_slot1[N_NODES];
__device__ int          g_slot2[N_NODES];
__device__ unsigned int g_bm1[BM_WORDS + 1];
__device__ unsigned int g_bm2[BM_WORDS + 1];
__device__ int   g_n1, g_n2, g_ne1, g_ne2;
__device__ int   g_s1_nodes[CAP1];
__device__ int   g_s2_nodes[CAP2];
__device__ int   g_e1_src[CAPE1];
__device__ int   g_e2_src[CAPE2];
__device__ int   g_e2_dslot[CAPE2];
__device__ float g_T0[NUM_RELS * H_DIM];      // T0[r][j] = W0[r][r][j]
__device__ float g_S[CAP2 * NUM_RELS];        // per-(S2-slot, rel) scalar sums
__device__ float g_msg1[CAP2 * H_DIM];
__device__ float g_root[H_DIM];               // node-0 layer-3 pre-activation

// software grid barrier (gen persists across graph replays; read at entry)
__device__ unsigned g_bar_cnt;
__device__ unsigned g_bar_gen;

#define GRID_SYNC()                                                         \
    do {                                                                    \
        __threadfence();  /* gpu-scope: also invalidates L1 (CCTL.IVALL) */ \
        __syncthreads();                                                    \
        if (threadIdx.x == 0) {                                             \
            if (atomicAdd(&g_bar_cnt, 1u) == (unsigned)(NB - 1)) {          \
                *(volatile unsigned*)&g_bar_cnt = 0u;                       \
                __threadfence();                                            \
                *(volatile unsigned*)&g_bar_gen = my_gen + 1u;              \
            } else {                                                        \
                while (*(volatile unsigned*)&g_bar_gen == my_gen)           \
                    __nanosleep(20);                                        \
            }                                                               \
            my_gen++;                                                       \
        }                                                                   \
        __syncthreads();                                                    \
    } while (0)

__global__ void __launch_bounds__(NT, 3) k_fused(
    const int* __restrict__ cls, const float* __restrict__ norm,
    const int* __restrict__ src, const int* __restrict__ dst,
    const float* __restrict__ W0, const float* __restrict__ W1,
    const float* __restrict__ W2,
    const float* __restrict__ a1_w, const float* __restrict__ a1_b,
    const float* __restrict__ a2_w, const float* __restrict__ a2_b,
    const float* __restrict__ c1_w, const float* __restrict__ c1_b,
    const float* __restrict__ c2_w, const float* __restrict__ c2_b,
    float* __restrict__ out, int out_size)
{
    const int tx   = threadIdx.x;
    const int bid  = blockIdx.x;
    const int gtid = bid * NT + tx;

    unsigned my_gen = 0;
    if (tx == 0) my_gen = *(volatile unsigned*)&g_bar_gen;

    __shared__ float sh[4][H_DIM];    // 4 GEMV groups of 128 threads
    __shared__ float s_red[H_DIM];
    __shared__ float s_hid[LIN_DIM];
    __shared__ float s_part[NT];
    __shared__ float s_mx, s_sum;

    // ---------------- phase 0: clear + build T0 ----------------
    {
        const int4 m1 = make_int4(-1, -1, -1, -1);
        const float4 z = make_float4(0.f, 0.f, 0.f, 0.f);
        for (int i = gtid; i < N_NODES / 4; i += GT) {
            reinterpret_cast<int4*>(g_slot1)[i] = m1;
            reinterpret_cast<int4*>(g_slot2)[i] = m1;
            if (i < (CAP2 * NUM_RELS) / 4) reinterpret_cast<float4*>(g_S)[i] = z;
            if (i <= BM_WORDS) { g_bm1[i] = 0u; g_bm2[i] = 0u; }
            if (i < NUM_RELS * H_DIM) {
                int r = i >> 7, j = i & 127;
                g_T0[i] = W0[(r * NUM_RELS + r) * H_DIM + j];
            }
            if (i < H_DIM) g_root[i] = 0.f;
        }
        if (gtid == 0) { g_n1 = 0; g_n2 = 0; g_ne1 = 0; g_ne2 = 0; }
    }
    GRID_SYNC();

    // ---------------- phase 1: dst == 0 -> S1 / E1 ----------------
    for (int i = gtid; i < NQ; i += GT) {
        const int4 d4 = reinterpret_cast<const int4*>(dst)[i];
        int dv[4] = {d4.x, d4.y, d4.z, d4.w};
#pragma unroll
        for (int k = 0; k < 4; k++) {
            if (dv[k] == 0) {
                int s = src[4 * i + k];
                int p = atomicAdd(&g_ne1, 1);
                if (p < CAPE1) g_e1_src[p] = s;
                if (atomicCAS(&g_slot1[s], -1, -2) == -1) {
                    int sl = atomicAdd(&g_n1, 1);
                    if (sl < CAP1) g_s1_nodes[sl] = s;
                    g_slot1[s] = sl;
                    atomicOr(&g_bm1[s >> 5], 1u << (s & 31));
                }
            }
        }
    }
    GRID_SYNC();

    // ---------------- phase 2: dst in S1 -> S2 / E2 ----------------
    for (int i = gtid; i < NQ; i += GT) {
        const int4 d4 = reinterpret_cast<const int4*>(dst)[i];
        int dv[4] = {d4.x, d4.y, d4.z, d4.w};
#pragma unroll
        for (int k = 0; k < 4; k++) {
            int d = dv[k];
            if (g_bm1[d >> 5] & (1u << (d & 31))) {
                int sl = g_slot1[d];
                if (sl >= 0 && sl < CAP1) {
                    int s = src[4 * i + k];
                    int p = atomicAdd(&g_ne2, 1);
                    if (p < CAPE2) { g_e2_src[p] = s; g_e2_dslot[p] = sl; }
                    if (atomicCAS(&g_slot2[s], -1, -2) == -1) {
                        int q = atomicAdd(&g_n2, 1);
                        if (q < CAP2) g_s2_nodes[q] = s;
                        g_slot2[s] = q;
                        atomicOr(&g_bm2[s >> 5], 1u << (s & 31));
                    }
                }
            }
        }
    }
    GRID_SYNC();

    // ---------------- phase 3: dst in S2 -> scalar rel-sums ----------------
    // S[slot2[dst]][cls[src]] += norm[src]   (ONE scalar atomic per hit)
    for (int i = gtid; i < NQ; i += GT) {
        const int4 d4 = reinterpret_cast<const int4*>(dst)[i];
        int dv[4] = {d4.x, d4.y, d4.z, d4.w};
#pragma unroll
        for (int k = 0; k < 4; k++) {
            int d = dv[k];
            if (g_bm2[d >> 5] & (1u << (d & 31))) {
                int sl = g_slot2[d];
                if (sl >= 0 && sl < CAP2) {
                    int s = src[4 * i + k];
                    atomicAdd(&g_S[sl * NUM_RELS + cls[s]], norm[s]);
                }
            }
        }
    }
    GRID_SYNC();

    // ---------------- phase 4: msg1 for S2 nodes ----------------
    // h1 = relu(S[sl] . T0);  msg1 = (h1 @ W1[cls]) * norm
    {
        int n2v = *(volatile int*)&g_n2; if (n2v > CAP2) n2v = CAP2;
        const int grp = tx >> 7;
        const int j   = tx & 127;
        const int per = NB * 4;
        for (int base = 0; base < n2v; base += per) {
            int sl = base + bid * 4 + grp;
            bool act = (sl < n2v);
            if (act) {
                const float* Sv = &g_S[sl * NUM_RELS];
                float h = 0.f;
#pragma unroll
                for (int r = 0; r < NUM_RELS; r++)
                    h = fmaf(Sv[r], g_T0[r * H_DIM + j], h);
                sh[grp][j] = fmaxf(h, 0.f);
            }
            __syncthreads();
            if (act) {
                int node = g_s2_nodes[sl];
                int c = cls[node];
                float nm = norm[node];
                const float* Wc = W1 + c * H_DIM * H_DIM;
                float a = 0.f;
#pragma unroll 8
                for (int k = 0; k < H_DIM; k++)
                    a = fmaf(sh[grp][k], Wc[k * H_DIM + j], a);
                g_msg1[sl * H_DIM + j] = a * nm;
            }
            __syncthreads();
        }
    }
    GRID_SYNC();

    // ---------------- phase 5: msg2 for S1 nodes + root accumulation ----------------
    // h2[w] = relu(sum over E2 edges into w of msg1[slot2[src]])
    // msg2 = (h2 @ W2[cls]) * norm ; root += multiplicity_in_E1(node) * msg2
    {
        int n1v = *(volatile int*)&g_n1;  if (n1v > CAP1)  n1v = CAP1;
        int ne2 = *(volatile int*)&g_ne2; if (ne2 > CAPE2) ne2 = CAPE2;
        int ne1 = *(volatile int*)&g_ne1; if (ne1 > CAPE1) ne1 = CAPE1;
        const int grp = tx >> 7;
        const int j   = tx & 127;
        const int per = NB * 4;
        for (int base = 0; base < n1v; base += per) {
            int sl = base + bid * 4 + grp;
            bool act = (sl < n1v);
            if (act) {
                float acc = 0.f;
                for (int e = 0; e < ne2; e++) {
                    if (g_e2_dslot[e] == sl) {
                        int ssl = g_slot2[g_e2_src[e]];
                        if (ssl >= 0 && ssl < CAP2) acc += g_msg1[ssl * H_DIM + j];
                    }
                }
                sh[grp][j] = fmaxf(acc, 0.f);
            }
            __syncthreads();
            if (act) {
                int node = g_s1_nodes[sl];
                int c = cls[node];
                float nm = norm[node];
                const float* Wc = W2 + c * H_DIM * H_DIM;
                float a = 0.f;
#pragma unroll 8
                for (int k = 0; k < H_DIM; k++)
                    a = fmaf(sh[grp][k], Wc[k * H_DIM + j], a);
                a *= nm;                       // msg2[j] for this node
                int mult = 0;
                for (int i = 0; i < ne1; i++) mult += (g_e1_src[i] == node);
                if (mult > 0) atomicAdd(&g_root[j], a * (float)mult);
            }
            __syncthreads();
        }
    }
    GRID_SYNC();

    // ---------------- phase 6: softmax + heads (block 0 only) ----------------
    if (bid != 0) return;
    {
        int t = tx;
        if (t < H_DIM) s_red[t] = g_root[t];
        __syncthreads();
        if (t == 0) {
            float mx = -1e30f;
            for (int i = 0; i < H_DIM; i++) mx = fmaxf(mx, s_red[i]);
            s_mx = mx;
        }
        __syncthreads();
        if (t < H_DIM) s_red[t] = expf(s_red[t] - s_mx);
        __syncthreads();
        if (t == 0) {
            float sm = 0.f;
            for (int i = 0; i < H_DIM; i++) sm += s_red[i];
            s_sum = sm;
        }
        __syncthreads();
        if (t < H_DIM) s_red[t] = s_red[t] / s_sum;    // root feats (probs over dims)
        __syncthreads();

        // actor: 128 -> 512 relu -> 128
        {
            float a = a1_b[t];
#pragma unroll 8
            for (int k = 0; k < H_DIM; k++) a = fmaf(s_red[k], a1_w[k * LIN_DIM + t], a);
            s_hid[t] = fmaxf(a, 0.f);
        }
        __syncthreads();
        if (t < H_DIM) {
            float a = a2_b[t];
#pragma unroll 8
            for (int k = 0; k < LIN_DIM; k++) a = fmaf(s_hid[k], a2_w[k * H_DIM + t], a);
            out[t] = a;
        }
        __syncthreads();

        // critic: 128 -> 512 relu -> 1
        {
            float a = c1_b[t];
#pragma unroll 8
            for (int k = 0; k < H_DIM; k++) a = fmaf(s_red[k], c1_w[k * LIN_DIM + t], a);
            s_hid[t] = fmaxf(a, 0.f);
        }
        __syncthreads();
        {
            float p = s_hid[t] * c2_w[t];
            s_part[t] = p;
        }
        __syncthreads();
        if (t == 0) {
            float a = c2_b[0];
            for (int i = 0; i < LIN_DIM; i++) a += s_part[i];
            if (out_size > H_DIM) out[H_DIM] = a;
        }
    }
}

// ---------------- launch ----------------
extern "C" void kernel_launch(void* const* d_in, const int* in_sizes, int n_in,
                              void* d_out, int out_size) {
    const int*   cls  = (const int*)  d_in[0];
    const float* norm = (const float*)d_in[1];
    const int*   src  = (const int*)  d_in[2];
    const int*   dst  = (const int*)  d_in[3];
    const float* W0   = (const float*)d_in[4];
    const float* W1   = (const float*)d_in[5];
    const float* W2   = (const float*)d_in[6];
    const float* a1_w = (const float*)d_in[7];
    const float* a1_b = (const float*)d_in[8];
    const float* a2_w = (const float*)d_in[9];
    const float* a2_b = (const float*)d_in[10];
    const float* c1_w = (const float*)d_in[11];
    const float* c1_b = (const float*)d_in[12];
    const float* c2_w = (const float*)d_in[13];
    const float* c2_b = (const float*)d_in[14];
    float* out = (float*)d_out;

    k_fused<<<NB, NT>>>(cls, norm, src, dst, W0, W1, W2,
                        a1_w, a1_b, a2_w, a2_b, c1_w, c1_b, c2_w, c2_b,
                        out, out_size);
}

// round 5
// speedup vs baseline: 1.2259x; 1.1323x over previous
#include <cuda_runtime.h>
#include <math.h>

#define N_NODES 50000
#define N_EDGES 800000
#define NUM_RELS 16
#define H_DIM 128
#define LIN_DIM 512

#define CAP1 256
#define CAP2 2048
#define CAPE1 512
#define CAPE2 4096

#define BM_WORDS ((N_NODES + 31) / 32)   // 1563

// scan config: single wave, 2 int4-quads per thread
#define SCAN_NB 196
#define SCAN_NT 512
#define NQ (N_EDGES / 4)                 // 200000

// ---------------- scratch (device globals; no allocation) ----------------
__device__ int          g_slot1[N_NODES];
__device__ int          g_slot2[N_NODES];
__device__ unsigned int g_bm1[BM_WORDS + 1];
__device__ unsigned int g_bm2[BM_WORDS + 1];
__device__ int   g_n1, g_n2, g_ne1, g_ne2;
__device__ int   g_s1_nodes[CAP1];
__device__ int   g_s2_nodes[CAP2];
__device__ int   g_e1_src[CAPE1];
__device__ int   g_e2_src[CAPE2];
__device__ int   g_e2_dslot[CAPE2];
__device__ float g_T0[NUM_RELS * H_DIM];   // T0[r][j] = W0[r][r][j]
__device__ float g_S[CAP2 * NUM_RELS];     // per-(S2-slot, rel) scalar sums
__device__ float g_msg1[CAP2 * H_DIM];
__device__ float g_root[H_DIM];            // node-0 layer-3 pre-activation

// ---------------- kernels ----------------

__global__ void __launch_bounds__(256) k_clear(const float* __restrict__ W0) {
    const int gtid = blockIdx.x * blockDim.x + threadIdx.x;
    const int GT = gridDim.x * blockDim.x;
    const int4 m1 = make_int4(-1, -1, -1, -1);
    const float4 z = make_float4(0.f, 0.f, 0.f, 0.f);
    for (int i = gtid; i < N_NODES / 4; i += GT) {
        reinterpret_cast<int4*>(g_slot1)[i] = m1;
        reinterpret_cast<int4*>(g_slot2)[i] = m1;
        if (i < (CAP2 * NUM_RELS) / 4) reinterpret_cast<float4*>(g_S)[i] = z;
        if (i <= BM_WORDS) { g_bm1[i] = 0u; g_bm2[i] = 0u; }
        if (i < NUM_RELS * H_DIM) {
            int r = i >> 7, j = i & 127;
            g_T0[i] = W0[(r * NUM_RELS + r) * H_DIM + j];   // one-hot @ W0[r]
        }
        if (i < H_DIM) g_root[i] = 0.f;
    }
    if (gtid == 0) { g_n1 = 0; g_n2 = 0; g_ne1 = 0; g_ne2 = 0; }
}

// Pass 1: edges with dst == 0 -> E1 list, register srcs into S1 (+bm1)
__global__ void __launch_bounds__(SCAN_NT) k_scan1(const int* __restrict__ src,
                                                   const int* __restrict__ dst) {
    const int gtid = blockIdx.x * blockDim.x + threadIdx.x;
    const int GT = SCAN_NB * SCAN_NT;
    for (int i = gtid; i < NQ; i += GT) {
        const int4 d4 = reinterpret_cast<const int4*>(dst)[i];
        int dv[4] = {d4.x, d4.y, d4.z, d4.w};
#pragma unroll
        for (int k = 0; k < 4; k++) {
            if (dv[k] == 0) {
                int s = src[4 * i + k];
                int p = atomicAdd(&g_ne1, 1);
                if (p < CAPE1) g_e1_src[p] = s;
                if (atomicCAS(&g_slot1[s], -1, -2) == -1) {
                    int sl = atomicAdd(&g_n1, 1);
                    if (sl < CAP1) g_s1_nodes[sl] = s;
                    g_slot1[s] = sl;
                    atomicOr(&g_bm1[s >> 5], 1u << (s & 31));
                }
            }
        }
    }
}

// Pass 2: edges with dst in S1 (bitmap fast-path) -> E2 list, register srcs into S2 (+bm2)
__global__ void __launch_bounds__(SCAN_NT) k_scan2(const int* __restrict__ src,
                                                   const int* __restrict__ dst) {
    const int gtid = blockIdx.x * blockDim.x + threadIdx.x;
    const int GT = SCAN_NB * SCAN_NT;
    for (int i = gtid; i < NQ; i += GT) {
        const int4 d4 = reinterpret_cast<const int4*>(dst)[i];
        int dv[4] = {d4.x, d4.y, d4.z, d4.w};
#pragma unroll
        for (int k = 0; k < 4; k++) {
            int d = dv[k];
            if (g_bm1[d >> 5] & (1u << (d & 31))) {
                int sl = g_slot1[d];
                if (sl >= 0 && sl < CAP1) {
                    int s = src[4 * i + k];
                    int p = atomicAdd(&g_ne2, 1);
                    if (p < CAPE2) { g_e2_src[p] = s; g_e2_dslot[p] = sl; }
                    if (atomicCAS(&g_slot2[s], -1, -2) == -1) {
                        int q = atomicAdd(&g_n2, 1);
                        if (q < CAP2) g_s2_nodes[q] = s;
                        g_slot2[s] = q;
                        atomicOr(&g_bm2[s >> 5], 1u << (s & 31));
                    }
                }
            }
        }
    }
}

// Pass 3: edges with dst in S2 -> ONE scalar atomic per hit:
// S[slot2[dst]][cls[src]] += norm[src]
__global__ void __launch_bounds__(SCAN_NT) k_scan3(const int* __restrict__ src,
                                                   const int* __restrict__ dst,
                                                   const int* __restrict__ cls,
                                                   const float* __restrict__ norm) {
    const int gtid = blockIdx.x * blockDim.x + threadIdx.x;
    const int GT = SCAN_NB * SCAN_NT;
    for (int i = gtid; i < NQ; i += GT) {
        const int4 d4 = reinterpret_cast<const int4*>(dst)[i];
        int dv[4] = {d4.x, d4.y, d4.z, d4.w};
#pragma unroll
        for (int k = 0; k < 4; k++) {
            int d = dv[k];
            if (g_bm2[d >> 5] & (1u << (d & 31))) {
                int sl = g_slot2[d];
                if (sl >= 0 && sl < CAP2) {
                    int s = src[4 * i + k];
                    atomicAdd(&g_S[sl * NUM_RELS + cls[s]], norm[s]);
                }
            }
        }
    }
}

// msg1 for S2: h1 = relu(S[sl] . T0); msg1 = (h1 @ W1[cls]) * norm
__global__ void __launch_bounds__(H_DIM) k_msg1(const int* __restrict__ cls,
                                                const float* __restrict__ norm,
                                                const float* __restrict__ W1) {
    const int j = threadIdx.x;
    __shared__ float sh[H_DIM];
    int n2 = g_n2; if (n2 > CAP2) n2 = CAP2;
    for (int sl = blockIdx.x; sl < n2; sl += gridDim.x) {
        const float* Sv = &g_S[sl * NUM_RELS];
        float h = 0.f;
#pragma unroll
        for (int r = 0; r < NUM_RELS; r++) h = fmaf(Sv[r], g_T0[r * H_DIM + j], h);
        sh[j] = fmaxf(h, 0.f);
        __syncthreads();
        int node = g_s2_nodes[sl];
        int c = cls[node];
        float nm = norm[node];
        const float* Wc = W1 + c * H_DIM * H_DIM;
        float a = 0.f;
#pragma unroll 8
        for (int k = 0; k < H_DIM; k++) a = fmaf(sh[k], Wc[k * H_DIM + j], a);
        g_msg1[sl * H_DIM + j] = a * nm;
        __syncthreads();
    }
}

// msg2 for S1 + node-0 root accumulation:
// h2 = relu(gather over E2); msg2 = (h2 @ W2[cls]) * norm;
// root += multiplicity_in_E1(node) * msg2
__global__ void __launch_bounds__(H_DIM) k_msg2root(const int* __restrict__ cls,
                                                    const float* __restrict__ norm,
                                                    const float* __restrict__ W2) {
    const int j = threadIdx.x;
    __shared__ float sh[H_DIM];
    int n1 = g_n1;  if (n1 > CAP1) n1 = CAP1;
    int ne2 = g_ne2; if (ne2 > CAPE2) ne2 = CAPE2;
    int ne1 = g_ne1; if (ne1 > CAPE1) ne1 = CAPE1;
    for (int sl = blockIdx.x; sl < n1; sl += gridDim.x) {
        float acc = 0.f;
        for (int e = 0; e < ne2; e++) {
            if (g_e2_dslot[e] == sl) {
                int ssl = g_slot2[g_e2_src[e]];
                if (ssl >= 0 && ssl < CAP2) acc += g_msg1[ssl * H_DIM + j];
            }
        }
        sh[j] = fmaxf(acc, 0.f);
        __syncthreads();
        int node = g_s1_nodes[sl];
        int c = cls[node];
        float nm = norm[node];
        const float* Wc = W2 + c * H_DIM * H_DIM;
        float a = 0.f;
#pragma unroll 8
        for (int k = 0; k < H_DIM; k++) a = fmaf(sh[k], Wc[k * H_DIM + j], a);
        a *= nm;
        int mult = 0;
        for (int i = 0; i < ne1; i++) mult += (g_e1_src[i] == node);
        if (mult > 0) atomicAdd(&g_root[j], a * (float)mult);
        __syncthreads();
    }
}

__device__ __forceinline__ float warp_max(float v) {
#pragma unroll
    for (int o = 16; o > 0; o >>= 1) v = fmaxf(v, __shfl_down_sync(0xffffffffu, v, o));
    return v;
}
__device__ __forceinline__ float warp_sum(float v) {
#pragma unroll
    for (int o = 16; o > 0; o >>= 1) v += __shfl_down_sync(0xffffffffu, v, o);
    return v;
}

// Final: softmax(root) + actor/critic heads. 1 block x 512 threads.
__global__ void __launch_bounds__(LIN_DIM) k_final(
        const float* __restrict__ a1_w, const float* __restrict__ a1_b,
        const float* __restrict__ a2_w, const float* __restrict__ a2_b,
        const float* __restrict__ c1_w, const float* __restrict__ c1_b,
        const float* __restrict__ c2_w, const float* __restrict__ c2_b,
        float* __restrict__ out, int out_size) {
    const int t = threadIdx.x;
    const int lane = t & 31;
    const int wid  = t >> 5;
    __shared__ float s_root[H_DIM];
    __shared__ float s_hid[LIN_DIM];
    __shared__ float s_part[LIN_DIM];
    __shared__ float s_r16[16];
    __shared__ float s_mx, s_sum;

    if (t < H_DIM) s_root[t] = g_root[t];
    __syncthreads();

    // softmax max: warp 0 covers 128 elems (4 per lane)
    if (wid == 0) {
        float m = fmaxf(fmaxf(s_root[lane], s_root[lane + 32]),
                        fmaxf(s_root[lane + 64], s_root[lane + 96]));
        m = warp_max(m);
        if (lane == 0) s_mx = m;
    }
    __syncthreads();
    if (t < H_DIM) s_root[t] = expf(s_root[t] - s_mx);
    __syncthreads();
    if (wid == 0) {
        float sm = s_root[lane] + s_root[lane + 32] + s_root[lane + 64] + s_root[lane + 96];
        sm = warp_sum(sm);
        if (lane == 0) s_sum = sm;
    }
    __syncthreads();
    if (t < H_DIM) s_root[t] *= (1.f / s_sum);
    __syncthreads();

    // actor1: 128 -> 512, relu (512 threads, one output each)
    {
        float a = a1_b[t];
#pragma unroll 8
        for (int k = 0; k < H_DIM; k++) a = fmaf(s_root[k], a1_w[k * LIN_DIM + t], a);
        s_hid[t] = fmaxf(a, 0.f);
    }
    __syncthreads();
    // actor2: 512 -> 128, 4-way k-split across 512 threads
    {
        int q = t >> 7, j = t & 127;
        const int k0 = q * 128;
        float p = 0.f;
#pragma unroll 8
        for (int k = 0; k < 128; k++) p = fmaf(s_hid[k0 + k], a2_w[(k0 + k) * H_DIM + j], p);
        s_part[t] = p;
    }
    __syncthreads();
    if (t < H_DIM)
        out[t] = a2_b[t] + s_part[t] + s_part[t + 128] + s_part[t + 256] + s_part[t + 384];
    __syncthreads();

    // critic1: 128 -> 512, relu
    {
        float a = c1_b[t];
#pragma unroll 8
        for (int k = 0; k < H_DIM; k++) a = fmaf(s_root[k], c1_w[k * LIN_DIM + t], a);
        s_hid[t] = fmaxf(a, 0.f);
    }
    __syncthreads();
    // critic2: 512 -> 1, warp-reduced
    {
        float p = warp_sum(s_hid[t] * c2_w[t]);
        if (lane == 0) s_r16[wid] = p;
    }
    __syncthreads();
    if (t == 0) {
        float a = c2_b[0];
#pragma unroll
        for (int i = 0; i < 16; i++) a += s_r16[i];
        if (out_size > H_DIM) out[H_DIM] = a;
    }
}

// ---------------- launch ----------------
extern "C" void kernel_launch(void* const* d_in, const int* in_sizes, int n_in,
                              void* d_out, int out_size) {
    const int*   cls  = (const int*)  d_in[0];
    const float* norm = (const float*)d_in[1];
    const int*   src  = (const int*)  d_in[2];
    const int*   dst  = (const int*)  d_in[3];
    const float* W0   = (const float*)d_in[4];
    const float* W1   = (const float*)d_in[5];
    const float* W2   = (const float*)d_in[6];
    const float* a1_w = (const float*)d_in[7];
    const float* a1_b = (const float*)d_in[8];
    const float* a2_w = (const float*)d_in[9];
    const float* a2_b = (const float*)d_in[10];
    const float* c1_w = (const float*)d_in[11];
    const float* c1_b = (const float*)d_in[12];
    const float* c2_w = (const float*)d_in[13];
    const float* c2_b = (const float*)d_in[14];
    float* out = (float*)d_out;

    k_clear<<<148, 256>>>(W0);
    k_scan1<<<SCAN_NB, SCAN_NT>>>(src, dst);
    k_scan2<<<SCAN_NB, SCAN_NT>>>(src, dst);
    k_scan3<<<SCAN_NB, SCAN_NT>>>(src, dst, cls, norm);
    k_msg1<<<256, H_DIM>>>(cls, norm, W1);
    k_msg2root<<<64, H_DIM>>>(cls, norm, W2);
    k_final<<<1, LIN_DIM>>>(a1_w, a1_b, a2_w, a2_b, c1_w, c1_b, c2_w, c2_b,
                            out, out_size);
}

// round 6
// speedup vs baseline: 1.5922x; 1.2988x over previous
#include <cuda_runtime.h>
#include <math.h>

#define N_NODES 50000
#define N_EDGES 800000
#define NUM_RELS 16
#define H_DIM 128
#define LIN_DIM 512

#define CAP1 256
#define CAP2 2048
#define CAPE1 512
#define CAPE2 4096
#define ESTG  2048          // smem staging cap for E2 list

#define BM_WORDS ((N_NODES + 31) / 32)

#define NB 444              // 3 blocks/SM on 148 SMs
#define NT 512
#define GT (NB * NT)        // 227328 >= NQ -> each thread <= 1 quad
#define NQ (N_EDGES / 4)    // 200000

// -------- scratch (device globals, zero-init is the valid empty state) --------
// slot encoding: 0 = absent, otherwise slot+1
__device__ int          g_slot1[N_NODES];
__device__ int          g_slot2[N_NODES];
__device__ unsigned int g_bm1[BM_WORDS + 1];
__device__ unsigned int g_bm2[BM_WORDS + 1];
__device__ int   g_n1, g_n2, g_ne1, g_ne2;
__device__ int   g_s1_nodes[CAP1];
__device__ int   g_s2_nodes[CAP2];
__device__ int   g_e1_src[CAPE1];
__device__ int   g_e2_src[CAPE2];
__device__ int   g_e2_dslot[CAPE2];          // 0-based slot1 of dst
__device__ float g_S[CAP2 * NUM_RELS];       // per-(S2-slot, rel) scalar sums
__device__ float g_msg1[CAP2 * H_DIM];
__device__ float g_root[H_DIM];

// persistent-generation grid barrier (state persists across graph replays)
__device__ unsigned g_bar_cnt;
__device__ unsigned g_bar_gen;

#define GRID_SYNC()                                                         \
    do {                                                                    \
        __threadfence();                                                    \
        __syncthreads();                                                    \
        if (threadIdx.x == 0) {                                             \
            if (atomicAdd(&g_bar_cnt, 1u) == (unsigned)(NB - 1)) {          \
                *(volatile unsigned*)&g_bar_cnt = 0u;                       \
                __threadfence();                                            \
                *(volatile unsigned*)&g_bar_gen = my_gen + 1u;              \
            } else {                                                        \
                while (*(volatile unsigned*)&g_bar_gen == my_gen)           \
                    __nanosleep(16);                                        \
            }                                                               \
            my_gen++;                                                       \
        }                                                                   \
        __syncthreads();                                                    \
    } while (0)

__device__ __forceinline__ float warp_max_f(float v) {
#pragma unroll
    for (int o = 16; o > 0; o >>= 1) v = fmaxf(v, __shfl_down_sync(0xffffffffu, v, o));
    return v;
}
__device__ __forceinline__ float warp_sum_f(float v) {
#pragma unroll
    for (int o = 16; o > 0; o >>= 1) v += __shfl_down_sync(0xffffffffu, v, o);
    return v;
}

__global__ void __launch_bounds__(NT, 3) k_fused(
    const int* __restrict__ cls, const float* __restrict__ norm,
    const int* __restrict__ src, const int* __restrict__ dst,
    const float* __restrict__ W0, const float* __restrict__ W1,
    const float* __restrict__ W2,
    const float* __restrict__ a1_w, const float* __restrict__ a1_b,
    const float* __restrict__ a2_w, const float* __restrict__ a2_b,
    const float* __restrict__ c1_w, const float* __restrict__ c1_b,
    const float* __restrict__ c2_w, const float* __restrict__ c2_b,
    float* __restrict__ out, int out_size)
{
    const int tx   = threadIdx.x;
    const int bid  = blockIdx.x;
    const int gtid = bid * NT + tx;

    unsigned my_gen = 0;
    if (tx == 0) my_gen = *(volatile unsigned*)&g_bar_gen;

    __shared__ int   sh_dsl[ESTG];
    __shared__ int   sh_ssl[ESTG];
    __shared__ int   sh_e1[CAPE1];
    __shared__ float sh_h[H_DIM];
    __shared__ float sh_p[NT];
    __shared__ float s_hid[LIN_DIM];
    __shared__ float s_mx, s_sum;

    // ---------- phase 1: dst == 0 -> S1 / E1 ----------
    if (gtid < NQ) {
        const int4 d4 = reinterpret_cast<const int4*>(dst)[gtid];
        int dv[4] = {d4.x, d4.y, d4.z, d4.w};
#pragma unroll
        for (int k = 0; k < 4; k++) {
            if (dv[k] == 0) {
                int s = src[4 * gtid + k];
                int p = atomicAdd(&g_ne1, 1);
                if (p < CAPE1) g_e1_src[p] = s;
                if (atomicCAS(&g_slot1[s], 0, -1) == 0) {
                    int sl = atomicAdd(&g_n1, 1);
                    if (sl < CAP1) g_s1_nodes[sl] = s;
                    g_slot1[s] = sl + 1;
                    atomicOr(&g_bm1[s >> 5], 1u << (s & 31));
                }
            }
        }
    }
    GRID_SYNC();

    // ---------- phase 2: dst in S1 -> S2 / E2 ----------
    if (gtid < NQ) {
        const int4 d4 = reinterpret_cast<const int4*>(dst)[gtid];
        int dv[4] = {d4.x, d4.y, d4.z, d4.w};
#pragma unroll
        for (int k = 0; k < 4; k++) {
            int d = dv[k];
            if (g_bm1[d >> 5] & (1u << (d & 31))) {
                int sl = g_slot1[d] - 1;
                if (sl >= 0 && sl < CAP1) {
                    int s = src[4 * gtid + k];
                    int p = atomicAdd(&g_ne2, 1);
                    if (p < CAPE2) { g_e2_src[p] = s; g_e2_dslot[p] = sl; }
                    if (atomicCAS(&g_slot2[s], 0, -1) == 0) {
                        int q = atomicAdd(&g_n2, 1);
                        if (q < CAP2) g_s2_nodes[q] = s;
                        g_slot2[s] = q + 1;
                        atomicOr(&g_bm2[s >> 5], 1u << (s & 31));
                    }
                }
            }
        }
    }
    GRID_SYNC();

    // ---------- phase 3: dst in S2 -> S[slot][cls[src]] += norm[src] ----------
    if (gtid < NQ) {
        const int4 d4 = reinterpret_cast<const int4*>(dst)[gtid];
        int dv[4] = {d4.x, d4.y, d4.z, d4.w};
#pragma unroll
        for (int k = 0; k < 4; k++) {
            int d = dv[k];
            if (g_bm2[d >> 5] & (1u << (d & 31))) {
                int sl = g_slot2[d] - 1;
                if (sl >= 0 && sl < CAP2) {
                    int s = src[4 * gtid + k];
                    atomicAdd(&g_S[sl * NUM_RELS + cls[s]], norm[s]);
                }
            }
        }
    }
    GRID_SYNC();

    // ---------- phase 4: msg1 for S2 nodes ----------
    // h1 = relu(S[sl] . T0) where T0[r][j] = W0[r][r][j]; msg1 = (h1 @ W1[c]) * nm
    {
        int n2v = *(volatile int*)&g_n2; if (n2v > CAP2) n2v = CAP2;
        const int j = tx & 127, q = tx >> 7;
        for (int sl = bid; sl < n2v; sl += NB) {
            if (tx < H_DIM) {
                const float* Sv = &g_S[sl * NUM_RELS];
                float h = 0.f;
#pragma unroll
                for (int r = 0; r < NUM_RELS; r++)
                    h = fmaf(Sv[r], W0[(r * NUM_RELS + r) * H_DIM + tx], h);
                sh_h[tx] = fmaxf(h, 0.f);
            }
            __syncthreads();
            int node = g_s2_nodes[sl];
            int c = cls[node];
            float nm = norm[node];
            const float* Wc = W1 + c * H_DIM * H_DIM;
            float p = 0.f;
#pragma unroll
            for (int kk = 0; kk < 32; kk++) {
                int k = q * 32 + kk;
                p = fmaf(sh_h[k], Wc[k * H_DIM + j], p);
            }
            sh_p[tx] = p;
            __syncthreads();
            if (tx < H_DIM)
                g_msg1[sl * H_DIM + tx] =
                    (sh_p[tx] + sh_p[tx + 128] + sh_p[tx + 256] + sh_p[tx + 384]) * nm;
            __syncthreads();
        }
    }
    GRID_SYNC();

    // ---------- phase 5: msg2 for S1 nodes + root accumulation ----------
    {
        int n1v = *(volatile int*)&g_n1;  if (n1v > CAP1)  n1v = CAP1;
        int ne2 = *(volatile int*)&g_ne2; if (ne2 > CAPE2) ne2 = CAPE2;
        int ne1 = *(volatile int*)&g_ne1; if (ne1 > CAPE1) ne1 = CAPE1;
        if (bid < n1v) {
            int nst = ne2 < ESTG ? ne2 : ESTG;
            for (int e = tx; e < nst; e += NT) {
                sh_dsl[e] = g_e2_dslot[e];
                sh_ssl[e] = g_slot2[g_e2_src[e]] - 1;
            }
            for (int i = tx; i < ne1; i += NT) sh_e1[i] = g_e1_src[i];
            __syncthreads();
            const int j = tx & 127, q = tx >> 7;
            for (int sl = bid; sl < n1v; sl += NB) {
                if (tx < H_DIM) {
                    float acc = 0.f;
                    for (int e = 0; e < nst; e++) {
                        if (sh_dsl[e] == sl) {
                            int ssl = sh_ssl[e];
                            if (ssl >= 0 && ssl < CAP2) acc += g_msg1[ssl * H_DIM + tx];
                        }
                    }
                    for (int e = nst; e < ne2; e++) {   // overflow fallback
                        if (g_e2_dslot[e] == sl) {
                            int ssl = g_slot2[g_e2_src[e]] - 1;
                            if (ssl >= 0 && ssl < CAP2) acc += g_msg1[ssl * H_DIM + tx];
                        }
                    }
                    sh_h[tx] = fmaxf(acc, 0.f);
                }
                __syncthreads();
                int node = g_s1_nodes[sl];
                int c = cls[node];
                float nm = norm[node];
                const float* Wc = W2 + c * H_DIM * H_DIM;
                float p = 0.f;
#pragma unroll
                for (int kk = 0; kk < 32; kk++) {
                    int k = q * 32 + kk;
                    p = fmaf(sh_h[k], Wc[k * H_DIM + j], p);
                }
                sh_p[tx] = p;
                __syncthreads();
                if (tx < H_DIM) {
                    float a = (sh_p[tx] + sh_p[tx + 128] + sh_p[tx + 256] + sh_p[tx + 384]) * nm;
                    int mult = 0;
                    for (int i = 0; i < ne1; i++) mult += (sh_e1[i] == node);
                    if (mult > 0) atomicAdd(&g_root[tx], a * (float)mult);
                }
                __syncthreads();
            }
        }
    }

    // ---------- last barrier: arrive; only blocks 0..2 continue ----------
    __threadfence();
    __syncthreads();
    if (tx == 0) {
        if (atomicAdd(&g_bar_cnt, 1u) == (unsigned)(NB - 1)) {
            *(volatile unsigned*)&g_bar_cnt = 0u;
            __threadfence();
            *(volatile unsigned*)&g_bar_gen = my_gen + 1u;
        } else if (bid < 3) {
            while (*(volatile unsigned*)&g_bar_gen == my_gen) __nanosleep(16);
        }
        my_gen++;
    }
    __syncthreads();
    if (bid >= 3) return;

    // ---------- epilogue: block1/2 clean state, block0 does heads ----------
    if (bid == 1) {
        int n1v = g_n1; if (n1v > CAP1) n1v = CAP1;
        for (int i = tx; i < n1v; i += NT) {
            int s = g_s1_nodes[i];
            g_slot1[s] = 0;
            g_bm1[s >> 5] = 0u;
        }
        __syncthreads();
        if (tx == 0) { g_n1 = 0; g_ne1 = 0; }
        return;
    }
    if (bid == 2) {
        int n2v = g_n2; if (n2v > CAP2) n2v = CAP2;
        for (int i = tx; i < n2v * NUM_RELS; i += NT) g_S[i] = 0.f;
        for (int i = tx; i < n2v; i += NT) {
            int s = g_s2_nodes[i];
            g_slot2[s] = 0;
            g_bm2[s >> 5] = 0u;
        }
        __syncthreads();
        if (tx == 0) { g_n2 = 0; g_ne2 = 0; }
        return;
    }

    // block 0: softmax(root) + actor/critic heads; then zero root
    {
        const int t = tx;
        const int lane = t & 31;
        const int wid  = t >> 5;
        if (t < H_DIM) sh_h[t] = g_root[t];
        __syncthreads();
        if (t < H_DIM) g_root[t] = 0.f;     // self-clean

        if (wid == 0) {
            float m = fmaxf(fmaxf(sh_h[lane], sh_h[lane + 32]),
                            fmaxf(sh_h[lane + 64], sh_h[lane + 96]));
            m = warp_max_f(m);
            if (lane == 0) s_mx = m;
        }
        __syncthreads();
        if (t < H_DIM) sh_h[t] = expf(sh_h[t] - s_mx);
        __syncthreads();
        if (wid == 0) {
            float sm = sh_h[lane] + sh_h[lane + 32] + sh_h[lane + 64] + sh_h[lane + 96];
            sm = warp_sum_f(sm);
            if (lane == 0) s_sum = sm;
        }
        __syncthreads();
        if (t < H_DIM) sh_h[t] *= (1.f / s_sum);    // root feats
        __syncthreads();

        // actor1: 128 -> 512 relu
        {
            float a = a1_b[t];
#pragma unroll 8
            for (int k = 0; k < H_DIM; k++) a = fmaf(sh_h[k], a1_w[k * LIN_DIM + t], a);
            s_hid[t] = fmaxf(a, 0.f);
        }
        __syncthreads();
        // actor2: 512 -> 128, 4-way k split
        {
            int q = t >> 7, j = t & 127;
            const int k0 = q * 128;
            float p = 0.f;
#pragma unroll 8
            for (int k = 0; k < 128; k++)
                p = fmaf(s_hid[k0 + k], a2_w[(k0 + k) * H_DIM + j], p);
            sh_p[t] = p;
        }
        __syncthreads();
        if (t < H_DIM)
            out[t] = a2_b[t] + sh_p[t] + sh_p[t + 128] + sh_p[t + 256] + sh_p[t + 384];
        __syncthreads();

        // critic: 128 -> 512 relu -> 1
        {
            float a = c1_b[t];
#pragma unroll 8
            for (int k = 0; k < H_DIM; k++) a = fmaf(sh_h[k], c1_w[k * LIN_DIM + t], a);
            s_hid[t] = fmaxf(a, 0.f);
        }
        __syncthreads();
        {
            float p = warp_sum_f(s_hid[t] * c2_w[t]);
            if (lane == 0) sh_p[wid] = p;
        }
        __syncthreads();
        if (t == 0) {
            float a = c2_b[0];
#pragma unroll
            for (int i = 0; i < 16; i++) a += sh_p[i];
            if (out_size > H_DIM) out[H_DIM] = a;
        }
    }
}

// ---------------- launch ----------------
extern "C" void kernel_launch(void* const* d_in, const int* in_sizes, int n_in,
                              void* d_out, int out_size) {
    const int*   cls  = (const int*)  d_in[0];
    const float* norm = (const float*)d_in[1];
    const int*   src  = (const int*)  d_in[2];
    const int*   dst  = (const int*)  d_in[3];
    const float* W0   = (const float*)d_in[4];
    const float* W1   = (const float*)d_in[5];
    const float* W2   = (const float*)d_in[6];
    const float* a1_w = (const float*)d_in[7];
    const float* a1_b = (const float*)d_in[8];
    const float* a2_w = (const float*)d_in[9];
    const float* a2_b = (const float*)d_in[10];
    const float* c1_w = (const float*)d_in[11];
    const float* c1_b = (const float*)d_in[12];
    const float* c2_w = (const float*)d_in[13];
    const float* c2_b = (const float*)d_in[14];
    float* out = (float*)d_out;

    k_fused<<<NB, NT>>>(cls, norm, src, dst, W0, W1, W2,
                        a1_w, a1_b, a2_w, a2_b, c1_w, c1_b, c2_w, c2_b,
                        out, out_size);
}

// round 7
// speedup vs baseline: 1.6008x; 1.0054x over previous
#include <cuda_runtime.h>
#include <math.h>

#define N_NODES 50000
#define N_EDGES 800000
#define NUM_RELS 16
#define H_DIM 128
#define LIN_DIM 512

#define CAP1 256
#define CAP2 2048
#define CAPE1 512
#define CAPE2 4096
#define ESTG  2048          // smem staging cap for E2 list

#define BM_WORDS ((N_NODES + 31) / 32)

#define NB 444              // 3 blocks/SM on 148 SMs
#define NT 512
#define GT (NB * NT)        // 227328 >= NQ -> each thread <= 1 quad
#define NQ (N_EDGES / 4)    // 200000

// -------- scratch (device globals, zero-init is the valid empty state) --------
// slot encoding: 0 = absent, otherwise slot+1
__device__ int          g_slot1[N_NODES];
__device__ int          g_slot2[N_NODES];
__device__ unsigned int g_bm1[BM_WORDS + 1];
__device__ unsigned int g_bm2[BM_WORDS + 1];
__device__ int   g_n1, g_n2, g_ne1, g_ne2;
__device__ int   g_s1_nodes[CAP1];
__device__ int   g_s2_nodes[CAP2];
__device__ int   g_e1_src[CAPE1];
__device__ int   g_e2_src[CAPE2];
__device__ int   g_e2_dslot[CAPE2];          // 0-based slot1 of dst
__device__ float g_S[CAP2 * NUM_RELS];       // per-(S2-slot, rel) scalar sums
__device__ float g_msg1[CAP2 * H_DIM];
__device__ float g_root[H_DIM];

// persistent-generation grid barrier (state persists across graph replays)
__device__ unsigned g_bar_cnt;
__device__ unsigned g_bar_gen;

// ---- release/acquire primitives (PTX memory model; no per-thread fences) ----
__device__ __forceinline__ unsigned atom_add_release_gpu(unsigned* p, unsigned v) {
    unsigned old;
    asm volatile("atom.add.release.gpu.u32 %0, [%1], %2;"
                 : "=r"(old) : "l"(p), "r"(v) : "memory");
    return old;
}
__device__ __forceinline__ unsigned ld_acquire_gpu(unsigned* p) {
    unsigned v;
    asm volatile("ld.acquire.gpu.u32 %0, [%1];" : "=r"(v) : "l"(p) : "memory");
    return v;
}
__device__ __forceinline__ void st_release_gpu(unsigned* p, unsigned v) {
    asm volatile("st.release.gpu.u32 [%0], %1;" :: "l"(p), "r"(v) : "memory");
}

// Happens-before chain: worker stores -> __syncthreads -> tx0 release-arrive ->
// peer tx0 acquire-load gen -> __syncthreads -> peer worker reads. (Same scheme
// as cooperative_groups::grid_group::sync.)
#define GRID_SYNC()                                                          \
    do {                                                                     \
        __syncthreads();                                                     \
        if (threadIdx.x == 0) {                                              \
            if (atom_add_release_gpu(&g_bar_cnt, 1u) == (unsigned)(NB - 1)) {\
                *(volatile unsigned*)&g_bar_cnt = 0u;                        \
                st_release_gpu(&g_bar_gen, my_gen + 1u);                     \
            } else {                                                         \
                int spin = 0;                                                \
                while (ld_acquire_gpu(&g_bar_gen) == my_gen)                 \
                    if (++spin > 64) __nanosleep(32);                        \
            }                                                                \
            my_gen++;                                                        \
        }                                                                    \
        __syncthreads();                                                     \
    } while (0)

__device__ __forceinline__ float warp_max_f(float v) {
#pragma unroll
    for (int o = 16; o > 0; o >>= 1) v = fmaxf(v, __shfl_down_sync(0xffffffffu, v, o));
    return v;
}
__device__ __forceinline__ float warp_sum_f(float v) {
#pragma unroll
    for (int o = 16; o > 0; o >>= 1) v += __shfl_down_sync(0xffffffffu, v, o);
    return v;
}

__global__ void __launch_bounds__(NT, 3) k_fused(
    const int* __restrict__ cls, const float* __restrict__ norm,
    const int* __restrict__ src, const int* __restrict__ dst,
    const float* __restrict__ W0, const float* __restrict__ W1,
    const float* __restrict__ W2,
    const float* __restrict__ a1_w, const float* __restrict__ a1_b,
    const float* __restrict__ a2_w, const float* __restrict__ a2_b,
    const float* __restrict__ c1_w, const float* __restrict__ c1_b,
    const float* __restrict__ c2_w, const float* __restrict__ c2_b,
    float* __restrict__ out, int out_size)
{
    const int tx   = threadIdx.x;
    const int bid  = blockIdx.x;
    const int gtid = bid * NT + tx;

    unsigned my_gen = 0;
    if (tx == 0) my_gen = ld_acquire_gpu(&g_bar_gen);

    __shared__ int   sh_dsl[ESTG];
    __shared__ int   sh_ssl[ESTG];
    __shared__ int   sh_e1[CAPE1];
    __shared__ float sh_h[H_DIM];
    __shared__ float sh_p[NT];
    __shared__ float s_hid[LIN_DIM];
    __shared__ float s_mx, s_sum;

    // ---------- phase 1: dst == 0 -> S1 / E1 ----------
    if (gtid < NQ) {
        const int4 d4 = reinterpret_cast<const int4*>(dst)[gtid];
        int dv[4] = {d4.x, d4.y, d4.z, d4.w};
#pragma unroll
        for (int k = 0; k < 4; k++) {
            if (dv[k] == 0) {
                int s = src[4 * gtid + k];
                int p = atomicAdd(&g_ne1, 1);
                if (p < CAPE1) g_e1_src[p] = s;
                if (atomicCAS(&g_slot1[s], 0, -1) == 0) {
                    int sl = atomicAdd(&g_n1, 1);
                    if (sl < CAP1) g_s1_nodes[sl] = s;
                    g_slot1[s] = sl + 1;
                    atomicOr(&g_bm1[s >> 5], 1u << (s & 31));
                }
            }
        }
    }
    GRID_SYNC();

    // ---------- phase 2: dst in S1 -> S2 / E2 ----------
    if (gtid < NQ) {
        const int4 d4 = reinterpret_cast<const int4*>(dst)[gtid];
        int dv[4] = {d4.x, d4.y, d4.z, d4.w};
#pragma unroll
        for (int k = 0; k < 4; k++) {
            int d = dv[k];
            if (g_bm1[d >> 5] & (1u << (d & 31))) {
                int sl = g_slot1[d] - 1;
                if (sl >= 0 && sl < CAP1) {
                    int s = src[4 * gtid + k];
                    int p = atomicAdd(&g_ne2, 1);
                    if (p < CAPE2) { g_e2_src[p] = s; g_e2_dslot[p] = sl; }
                    if (atomicCAS(&g_slot2[s], 0, -1) == 0) {
                        int q = atomicAdd(&g_n2, 1);
                        if (q < CAP2) g_s2_nodes[q] = s;
                        g_slot2[s] = q + 1;
                        atomicOr(&g_bm2[s >> 5], 1u << (s & 31));
                    }
                }
            }
        }
    }
    GRID_SYNC();

    // ---------- phase 3: dst in S2 -> S[slot][cls[src]] += norm[src] ----------
    if (gtid < NQ) {
        const int4 d4 = reinterpret_cast<const int4*>(dst)[gtid];
        int dv[4] = {d4.x, d4.y, d4.z, d4.w};
#pragma unroll
        for (int k = 0; k < 4; k++) {
            int d = dv[k];
            if (g_bm2[d >> 5] & (1u << (d & 31))) {
                int sl = g_slot2[d] - 1;
                if (sl >= 0 && sl < CAP2) {
                    int s = src[4 * gtid + k];
                    atomicAdd(&g_S[sl * NUM_RELS + cls[s]], norm[s]);
                }
            }
        }
    }
    GRID_SYNC();

    // ---------- phase 4: msg1 for S2 nodes ----------
    // h1 = relu(S[sl] . T0) where T0[r][j] = W0[r][r][j]; msg1 = (h1 @ W1[c]) * nm
    {
        int n2v = *(volatile int*)&g_n2; if (n2v > CAP2) n2v = CAP2;
        const int j = tx & 127, q = tx >> 7;
        for (int sl = bid; sl < n2v; sl += NB) {
            if (tx < H_DIM) {
                const float* Sv = &g_S[sl * NUM_RELS];
                float h = 0.f;
#pragma unroll
                for (int r = 0; r < NUM_RELS; r++)
                    h = fmaf(Sv[r], W0[(r * NUM_RELS + r) * H_DIM + tx], h);
                sh_h[tx] = fmaxf(h, 0.f);
            }
            __syncthreads();
            int node = g_s2_nodes[sl];
            int c = cls[node];
            float nm = norm[node];
            const float* Wc = W1 + c * H_DIM * H_DIM;
            float p = 0.f;
#pragma unroll
            for (int kk = 0; kk < 32; kk++) {
                int k = q * 32 + kk;
                p = fmaf(sh_h[k], Wc[k * H_DIM + j], p);
            }
            sh_p[tx] = p;
            __syncthreads();
            if (tx < H_DIM)
                g_msg1[sl * H_DIM + tx] =
                    (sh_p[tx] + sh_p[tx + 128] + sh_p[tx + 256] + sh_p[tx + 384]) * nm;
            __syncthreads();
        }
    }
    GRID_SYNC();

    // ---------- phase 5: msg2 for S1 nodes + root accumulation ----------
    {
        int n1v = *(volatile int*)&g_n1;  if (n1v > CAP1)  n1v = CAP1;
        int ne2 = *(volatile int*)&g_ne2; if (ne2 > CAPE2) ne2 = CAPE2;
        int ne1 = *(volatile int*)&g_ne1; if (ne1 > CAPE1) ne1 = CAPE1;
        if (bid < n1v) {
            int nst = ne2 < ESTG ? ne2 : ESTG;
            for (int e = tx; e < nst; e += NT) {
                sh_dsl[e] = g_e2_dslot[e];
                sh_ssl[e] = g_slot2[g_e2_src[e]] - 1;
            }
            for (int i = tx; i < ne1; i += NT) sh_e1[i] = g_e1_src[i];
            __syncthreads();
            const int j = tx & 127, q = tx >> 7;
            for (int sl = bid; sl < n1v; sl += NB) {
                if (tx < H_DIM) {
                    float acc = 0.f;
                    for (int e = 0; e < nst; e++) {
                        if (sh_dsl[e] == sl) {
                            int ssl = sh_ssl[e];
                            if (ssl >= 0 && ssl < CAP2) acc += g_msg1[ssl * H_DIM + tx];
                        }
                    }
                    for (int e = nst; e < ne2; e++) {   // overflow fallback
                        if (g_e2_dslot[e] == sl) {
                            int ssl = g_slot2[g_e2_src[e]] - 1;
                            if (ssl >= 0 && ssl < CAP2) acc += g_msg1[ssl * H_DIM + tx];
                        }
                    }
                    sh_h[tx] = fmaxf(acc, 0.f);
                }
                __syncthreads();
                int node = g_s1_nodes[sl];
                int c = cls[node];
                float nm = norm[node];
                const float* Wc = W2 + c * H_DIM * H_DIM;
                float p = 0.f;
#pragma unroll
                for (int kk = 0; kk < 32; kk++) {
                    int k = q * 32 + kk;
                    p = fmaf(sh_h[k], Wc[k * H_DIM + j], p);
                }
                sh_p[tx] = p;
                __syncthreads();
                if (tx < H_DIM) {
                    float a = (sh_p[tx] + sh_p[tx + 128] + sh_p[tx + 256] + sh_p[tx + 384]) * nm;
                    int mult = 0;
                    for (int i = 0; i < ne1; i++) mult += (sh_e1[i] == node);
                    if (mult > 0) atomicAdd(&g_root[tx], a * (float)mult);
                }
                __syncthreads();
            }
        }
    }

    // ---------- last barrier: arrive (release); only blocks 0..2 wait ----------
    __syncthreads();
    if (tx == 0) {
        if (atom_add_release_gpu(&g_bar_cnt, 1u) == (unsigned)(NB - 1)) {
            *(volatile unsigned*)&g_bar_cnt = 0u;
            st_release_gpu(&g_bar_gen, my_gen + 1u);
        } else if (bid < 3) {
            int spin = 0;
            while (ld_acquire_gpu(&g_bar_gen) == my_gen)
                if (++spin > 64) __nanosleep(32);
        }
        my_gen++;
    }
    __syncthreads();
    if (bid >= 3) return;

    // ---------- epilogue: block1/2 clean state, block0 does heads ----------
    if (bid == 1) {
        int n1v = g_n1; if (n1v > CAP1) n1v = CAP1;
        for (int i = tx; i < n1v; i += NT) {
            int s = g_s1_nodes[i];
            g_slot1[s] = 0;
            g_bm1[s >> 5] = 0u;
        }
        __syncthreads();
        if (tx == 0) { g_n1 = 0; g_ne1 = 0; }
        return;
    }
    if (bid == 2) {
        int n2v = g_n2; if (n2v > CAP2) n2v = CAP2;
        for (int i = tx; i < n2v * NUM_RELS; i += NT) g_S[i] = 0.f;
        for (int i = tx; i < n2v; i += NT) {
            int s = g_s2_nodes[i];
            g_slot2[s] = 0;
            g_bm2[s >> 5] = 0u;
        }
        __syncthreads();
        if (tx == 0) { g_n2 = 0; g_ne2 = 0; }
        return;
    }

    // block 0: softmax(root) + actor/critic heads; then zero root
    {
        const int t = tx;
        const int lane = t & 31;
        const int wid  = t >> 5;
        if (t < H_DIM) sh_h[t] = g_root[t];
        __syncthreads();
        if (t < H_DIM) g_root[t] = 0.f;     // self-clean

        if (wid == 0) {
            float m = fmaxf(fmaxf(sh_h[lane], sh_h[lane + 32]),
                            fmaxf(sh_h[lane + 64], sh_h[lane + 96]));
            m = warp_max_f(m);
            if (lane == 0) s_mx = m;
        }
        __syncthreads();
        if (t < H_DIM) sh_h[t] = expf(sh_h[t] - s_mx);
        __syncthreads();
        if (wid == 0) {
            float sm = sh_h[lane] + sh_h[lane + 32] + sh_h[lane + 64] + sh_h[lane + 96];
            sm = warp_sum_f(sm);
            if (lane == 0) s_sum = sm;
        }
        __syncthreads();
        if (t < H_DIM) sh_h[t] *= (1.f / s_sum);    // root feats
        __syncthreads();

        // actor1: 128 -> 512 relu
        {
            float a = a1_b[t];
#pragma unroll 8
            for (int k = 0; k < H_DIM; k++) a = fmaf(sh_h[k], a1_w[k * LIN_DIM + t], a);
            s_hid[t] = fmaxf(a, 0.f);
        }
        __syncthreads();
        // actor2: 512 -> 128, 4-way k split
        {
            int q = t >> 7, j = t & 127;
            const int k0 = q * 128;
            float p = 0.f;
#pragma unroll 8
            for (int k = 0; k < 128; k++)
                p = fmaf(s_hid[k0 + k], a2_w[(k0 + k) * H_DIM + j], p);
            sh_p[t] = p;
        }
        __syncthreads();
        if (t < H_DIM)
            out[t] = a2_b[t] + sh_p[t] + sh_p[t + 128] + sh_p[t + 256] + sh_p[t + 384];
        __syncthreads();

        // critic: 128 -> 512 relu -> 1
        {
            float a = c1_b[t];
#pragma unroll 8
            for (int k = 0; k < H_DIM; k++) a = fmaf(sh_h[k], c1_w[k * LIN_DIM + t], a);
            s_hid[t] = fmaxf(a, 0.f);
        }
        __syncthreads();
        {
            float p = warp_sum_f(s_hid[t] * c2_w[t]);
            if (lane == 0) sh_p[wid] = p;
        }
        __syncthreads();
        if (t == 0) {
            float a = c2_b[0];
#pragma unroll
            for (int i = 0; i < 16; i++) a += sh_p[i];
            if (out_size > H_DIM) out[H_DIM] = a;
        }
    }
}

// ---------------- launch ----------------
extern "C" void kernel_launch(void* const* d_in, const int* in_sizes, int n_in,
                              void* d_out, int out_size) {
    const int*   cls  = (const int*)  d_in[0];
    const float* norm = (const float*)d_in[1];
    const int*   src  = (const int*)  d_in[2];
    const int*   dst  = (const int*)  d_in[3];
    const float* W0   = (const float*)d_in[4];
    const float* W1   = (const float*)d_in[5];
    const float* W2   = (const float*)d_in[6];
    const float* a1_w = (const float*)d_in[7];
    const float* a1_b = (const float*)d_in[8];
    const float* a2_w = (const float*)d_in[9];
    const float* a2_b = (const float*)d_in[10];
    const float* c1_w = (const float*)d_in[11];
    const float* c1_b = (const float*)d_in[12];
    const float* c2_w = (const float*)d_in[13];
    const float* c2_b = (const float*)d_in[14];
    float* out = (float*)d_out;

    k_fused<<<NB, NT>>>(cls, norm, src, dst, W0, W1, W2,
                        a1_w, a1_b, a2_w, a2_b, c1_w, c1_b, c2_w, c2_b,
                        out, out_size);
}